// round 1
// baseline (speedup 1.0000x reference)
#include <cuda_runtime.h>
#include <cuda_bf16.h>
#include <mma.h>
#include <math.h>

using namespace nvcuda;

#define CCH 512
#define GRP 32
#define AREA 4096
#define BATCH 4
#define EPS 1e-6f

// ---------------- scratch (device globals; no runtime allocation) ----------------
__device__ float g_xn[(size_t)BATCH * CCH * AREA];   // 32 MB
__device__ float g_q [(size_t)BATCH * CCH * AREA];
__device__ float g_k [(size_t)BATCH * CCH * AREA];
__device__ float g_v [(size_t)BATCH * CCH * AREA];
__device__ float g_h [(size_t)BATCH * CCH * AREA];
__device__ float g_s [(size_t)BATCH * AREA * AREA]; // 256 MB

// ---------------- GroupNorm ----------------
// one block per (batch, group); 16 channels x 4096 pixels = 65536 elems
__global__ void groupnorm_kernel(const float* __restrict__ net,
                                 const float* __restrict__ gscale,
                                 const float* __restrict__ gbias,
                                 float* __restrict__ xn) {
    const int CPG = CCH / GRP;           // 16
    const int NEL = CPG * AREA;          // 65536
    int bg = blockIdx.x;
    int b = bg / GRP, g = bg % GRP;
    const float* x = net + ((size_t)b * CCH + (size_t)g * CPG) * AREA;
    float* y = xn + ((size_t)b * CCH + (size_t)g * CPG) * AREA;

    int tid = threadIdx.x;
    float s = 0.f, ss = 0.f;
    for (int i = tid; i < NEL; i += blockDim.x) {
        float v = x[i];
        s += v; ss += v * v;
    }
    __shared__ float rs[256], rss[256];
    rs[tid] = s; rss[tid] = ss;
    __syncthreads();
    for (int o = 128; o > 0; o >>= 1) {
        if (tid < o) { rs[tid] += rs[tid + o]; rss[tid] += rss[tid + o]; }
        __syncthreads();
    }
    float mu  = rs[0] / (float)NEL;
    float var = rss[0] / (float)NEL - mu * mu;
    float inv = rsqrtf(var + EPS);

    for (int i = tid; i < NEL; i += blockDim.x) {
        int cl = i / AREA;
        int c  = g * CPG + cl;
        y[i] = (x[i] - mu) * inv * gscale[c] + gbias[c];
    }
}

// ---------------- generic TF32 WMMA GEMM ----------------
// C[m,n] = alpha * sum_k A(m,k)*B(k,n)  [+ bias[m]] [+ res[m*ldc+n]]
// C always row-major. A_COL: A(m,k) = A[k*lda+m]; else A[m*lda+k].
// B_COL: B(k,n) = B[n*ldb+k]; else B[k*ldb+n].
#define BM 64
#define BN 64
#define BKT 32
#define PAD 8

template<bool A_COL, bool B_COL>
__global__ void __launch_bounds__(128)
gemm_tf32_kernel(const float* __restrict__ A, const float* __restrict__ B,
                 float* __restrict__ C,
                 const float* __restrict__ bias, const float* __restrict__ res,
                 int M, int N, int K, int lda, int ldb, int ldc,
                 long strideA, long strideB, long strideC, long strideRes,
                 float alpha) {
    int bz = blockIdx.z;
    A += (size_t)bz * strideA;
    B += (size_t)bz * strideB;
    C += (size_t)bz * strideC;
    if (res) res += (size_t)bz * strideRes;

    int bm = blockIdx.y * BM;
    int bn = blockIdx.x * BN;

    __shared__ float sA[BM][BKT + PAD];
    __shared__ float sB[BKT][BN + PAD];
    __shared__ float sC[BM][BN + PAD];

    int tid = threadIdx.x;        // 128 threads = 4 warps
    int warp = tid >> 5;
    int wm = warp >> 1;           // 0..1
    int wn = warp & 1;            // 0..1  -> each warp computes 32x32

    wmma::fragment<wmma::accumulator, 16, 16, 8, float> acc[2][2];
    #pragma unroll
    for (int i = 0; i < 2; i++)
        #pragma unroll
        for (int j = 0; j < 2; j++)
            wmma::fill_fragment(acc[i][j], 0.0f);

    for (int k0 = 0; k0 < K; k0 += BKT) {
        // load A tile (normalize to row-major [m][k])
        #pragma unroll 4
        for (int i = tid; i < BM * BKT; i += 128) {
            int m = i / BKT, k = i % BKT;
            sA[m][k] = A_COL ? A[(size_t)(k0 + k) * lda + (bm + m)]
                             : A[(size_t)(bm + m) * lda + (k0 + k)];
        }
        // load B tile (normalize to row-major [k][n])
        #pragma unroll 4
        for (int i = tid; i < BKT * BN; i += 128) {
            int k = i / BN, n = i % BN;
            sB[k][n] = B_COL ? B[(size_t)(bn + n) * ldb + (k0 + k)]
                             : B[(size_t)(k0 + k) * ldb + (bn + n)];
        }
        __syncthreads();

        #pragma unroll
        for (int kk = 0; kk < BKT; kk += 8) {
            wmma::fragment<wmma::matrix_a, 16, 16, 8, wmma::precision::tf32, wmma::row_major> fa[2];
            wmma::fragment<wmma::matrix_b, 16, 16, 8, wmma::precision::tf32, wmma::row_major> fb[2];
            #pragma unroll
            for (int im = 0; im < 2; im++) {
                wmma::load_matrix_sync(fa[im], &sA[wm * 32 + im * 16][kk], BKT + PAD);
                #pragma unroll
                for (int t = 0; t < fa[im].num_elements; t++)
                    fa[im].x[t] = wmma::__float_to_tf32(fa[im].x[t]);
            }
            #pragma unroll
            for (int in_ = 0; in_ < 2; in_++) {
                wmma::load_matrix_sync(fb[in_], &sB[kk][wn * 32 + in_ * 16], BN + PAD);
                #pragma unroll
                for (int t = 0; t < fb[in_].num_elements; t++)
                    fb[in_].x[t] = wmma::__float_to_tf32(fb[in_].x[t]);
            }
            #pragma unroll
            for (int im = 0; im < 2; im++)
                #pragma unroll
                for (int in_ = 0; in_ < 2; in_++)
                    wmma::mma_sync(acc[im][in_], fa[im], fb[in_], acc[im][in_]);
        }
        __syncthreads();
    }

    // epilogue via smem staging
    #pragma unroll
    for (int im = 0; im < 2; im++)
        #pragma unroll
        for (int in_ = 0; in_ < 2; in_++)
            wmma::store_matrix_sync(&sC[wm * 32 + im * 16][wn * 32 + in_ * 16],
                                    acc[im][in_], BN + PAD, wmma::mem_row_major);
    __syncthreads();

    for (int i = tid; i < BM * BN; i += 128) {
        int m = i / BN, n = i % BN;
        int gm = bm + m, gn = bn + n;
        if (gm < M && gn < N) {
            float v = alpha * sC[m][n];
            if (bias) v += bias[gm];
            if (res)  v += res[(size_t)gm * ldc + gn];
            C[(size_t)gm * ldc + gn] = v;
        }
    }
}

// ---------------- row softmax (in-place), rows of length AREA ----------------
__global__ void softmax_kernel(float* __restrict__ S) {
    float* row = S + (size_t)blockIdx.x * AREA;
    __shared__ float buf[AREA];
    __shared__ float red[256];
    int tid = threadIdx.x;

    float m = -INFINITY;
    for (int i = tid; i < AREA; i += 256) {
        float v = row[i];
        buf[i] = v;
        m = fmaxf(m, v);
    }
    red[tid] = m;
    __syncthreads();
    for (int o = 128; o > 0; o >>= 1) {
        if (tid < o) red[tid] = fmaxf(red[tid], red[tid + o]);
        __syncthreads();
    }
    m = red[0];
    __syncthreads();

    float s = 0.f;
    for (int i = tid; i < AREA; i += 256) {
        float e = __expf(buf[i] - m);
        buf[i] = e;
        s += e;
    }
    red[tid] = s;
    __syncthreads();
    for (int o = 128; o > 0; o >>= 1) {
        if (tid < o) red[tid] += red[tid + o];
        __syncthreads();
    }
    float inv = 1.0f / red[0];
    __syncthreads();

    for (int i = tid; i < AREA; i += 256)
        row[i] = buf[i] * inv;
}

// ---------------- launch ----------------
extern "C" void kernel_launch(void* const* d_in, const int* in_sizes, int n_in,
                              void* d_out, int out_size) {
    const float* net      = (const float*)d_in[0];
    const float* gn_scale = (const float*)d_in[1];
    const float* gn_bias  = (const float*)d_in[2];
    const float* wq = (const float*)d_in[3];
    const float* bq = (const float*)d_in[4];
    const float* wk = (const float*)d_in[5];
    const float* bk = (const float*)d_in[6];
    const float* wv = (const float*)d_in[7];
    const float* bv = (const float*)d_in[8];
    const float* wo = (const float*)d_in[9];
    const float* bo = (const float*)d_in[10];
    float* out = (float*)d_out;

    float *xn, *q, *k, *v, *h, *s;
    cudaGetSymbolAddress((void**)&xn, g_xn);
    cudaGetSymbolAddress((void**)&q,  g_q);
    cudaGetSymbolAddress((void**)&k,  g_k);
    cudaGetSymbolAddress((void**)&v,  g_v);
    cudaGetSymbolAddress((void**)&h,  g_h);
    cudaGetSymbolAddress((void**)&s,  g_s);

    const long sBC = (long)CCH * AREA;     // per-batch stride for [C, area]
    const long sSS = (long)AREA * AREA;    // per-batch stride for [area, area]
    const float inv_sqrt_c = 1.0f / sqrtf((float)CCH);

    // 1. GroupNorm
    groupnorm_kernel<<<BATCH * GRP, 256>>>(net, gn_scale, gn_bias, xn);

    // 2. Q/K/V = W @ xn + b  (M=512, N=4096, K=512)
    dim3 gProj(AREA / BN, CCH / BM, BATCH);
    gemm_tf32_kernel<false, false><<<gProj, 128>>>(wq, xn, q, bq, nullptr,
        CCH, AREA, CCH, CCH, AREA, AREA, 0, sBC, sBC, 0, 1.0f);
    gemm_tf32_kernel<false, false><<<gProj, 128>>>(wk, xn, k, bk, nullptr,
        CCH, AREA, CCH, CCH, AREA, AREA, 0, sBC, sBC, 0, 1.0f);
    gemm_tf32_kernel<false, false><<<gProj, 128>>>(wv, xn, v, bv, nullptr,
        CCH, AREA, CCH, CCH, AREA, AREA, 0, sBC, sBC, 0, 1.0f);

    // 3. S = (Q^T K) / sqrt(C)   (M=4096, N=4096, K=512); A col-major view of q
    dim3 gScore(AREA / BN, AREA / BM, BATCH);
    gemm_tf32_kernel<true, false><<<gScore, 128>>>(q, k, s, nullptr, nullptr,
        AREA, AREA, CCH, AREA, AREA, AREA, sBC, sBC, sSS, 0, inv_sqrt_c);

    // 4. softmax over keys (rows of S)
    softmax_kernel<<<BATCH * AREA, 256>>>(s);

    // 5. H = V @ P^T  (M=512, N=4096, K=4096); B col-major view of P
    dim3 gPV(AREA / BN, CCH / BM, BATCH);
    gemm_tf32_kernel<false, true><<<gPV, 128>>>(v, s, h, nullptr, nullptr,
        CCH, AREA, AREA, AREA, AREA, AREA, sBC, sSS, sBC, 0, 1.0f);

    // 6. out = net + Wo @ H + bo  (M=512, N=4096, K=512)
    gemm_tf32_kernel<false, false><<<gProj, 128>>>(wo, h, out, bo, net,
        CCH, AREA, CCH, CCH, AREA, AREA, 0, sBC, sBC, sBC, 1.0f);
}

// round 3
// speedup vs baseline: 2.1765x; 2.1765x over previous
#include <cuda_runtime.h>
#include <cstdint>
#include <mma.h>
#include <math.h>

using namespace nvcuda;

#define CCH 512
#define GRP 32
#define AREA 4096
#define BATCH 4
#define EPS 1e-6f

// ---------------- scratch (device globals) ----------------
__device__ float g_xn  [(size_t)BATCH * CCH * AREA];       // 32 MB
__device__ float g_qkv [(size_t)BATCH * 3 * CCH * AREA];   // 96 MB (q|k|v per batch)
__device__ float g_h   [(size_t)BATCH * CCH * AREA];       // 32 MB
__device__ float g_s   [(size_t)BATCH * AREA * AREA];      // 256 MB
__device__ float g_wqkv[3 * CCH * CCH];
__device__ float g_bqkv[3 * CCH];

// ---------------- GroupNorm ----------------
__global__ void groupnorm_kernel(const float* __restrict__ net,
                                 const float* __restrict__ gscale,
                                 const float* __restrict__ gbias,
                                 float* __restrict__ xn) {
    const int CPG = CCH / GRP;           // 16
    const int NEL = CPG * AREA;          // 65536
    int bg = blockIdx.x;
    int b = bg / GRP, g = bg % GRP;
    const float* x = net + ((size_t)b * CCH + (size_t)g * CPG) * AREA;
    float* y = xn + ((size_t)b * CCH + (size_t)g * CPG) * AREA;

    int tid = threadIdx.x;
    float s = 0.f, ss = 0.f;
    for (int i = tid; i < NEL; i += blockDim.x) {
        float v = x[i];
        s += v; ss += v * v;
    }
    __shared__ float rs[256], rss[256];
    rs[tid] = s; rss[tid] = ss;
    __syncthreads();
    for (int o = 128; o > 0; o >>= 1) {
        if (tid < o) { rs[tid] += rs[tid + o]; rss[tid] += rss[tid + o]; }
        __syncthreads();
    }
    float mu  = rs[0] / (float)NEL;
    float var = rss[0] / (float)NEL - mu * mu;
    float inv = rsqrtf(var + EPS);

    for (int i = tid; i < NEL; i += blockDim.x) {
        int cl = i / AREA;
        int c  = g * CPG + cl;
        y[i] = (x[i] - mu) * inv * gscale[c] + gbias[c];
    }
}

// ---------------- pack QKV weights/biases ----------------
__global__ void pack_qkv_kernel(const float* __restrict__ wq, const float* __restrict__ wk,
                                const float* __restrict__ wv, const float* __restrict__ bq,
                                const float* __restrict__ bk, const float* __restrict__ bv,
                                float* __restrict__ w, float* __restrict__ b) {
    int i = blockIdx.x * blockDim.x + threadIdx.x;
    const int WN = CCH * CCH;
    if (i < WN) {
        w[i] = wq[i];
        w[i + WN] = wk[i];
        w[i + 2 * WN] = wv[i];
    }
    if (i < CCH) {
        b[i] = bq[i];
        b[i + CCH] = bk[i];
        b[i + 2 * CCH] = bv[i];
    }
}

// ---------------- double-buffered TF32 WMMA GEMM, 128x128x32 ----------------
// C[m,n] = alpha * sum_k A(m,k)*B(k,n)  [+ bias[m]] [+ res[...]]
// A_COL: A(m,k)=A[k*lda+m]  (else A[m*lda+k]);  B_COL: B(k,n)=B[n*ldb+k] (else B[k*ldb+n])
#define BM 128
#define BN 128
#define BK 32

template<bool C_> struct CondLay;
template<> struct CondLay<false> { using type = wmma::row_major; };
template<> struct CondLay<true>  { using type = wmma::col_major; };

__device__ __forceinline__ void cp16(void* s, const void* g) {
    unsigned int sa = (unsigned int)__cvta_generic_to_shared(s);
    asm volatile("cp.async.cg.shared.global [%0], [%1], 16;" :: "r"(sa), "l"(g));
}

template<bool A_COL, bool B_COL>
__global__ void __launch_bounds__(256)
gemm_tf32(const float* __restrict__ A, const float* __restrict__ B,
          float* __restrict__ C,
          const float* __restrict__ bias, const float* __restrict__ res,
          int M, int N, int K, int lda, int ldb, int ldc,
          long strA, long strB, long strC, long strR, float alpha) {
    extern __shared__ float smem[];
    // smem tile layouts (floats):
    //  A row-major: [BM][36] ; A col-major: [BK][132]
    //  B row-major: [BK][132]; B col-major: [BN][36]
    constexpr int A_ELEMS = A_COL ? BK * 132 : BM * 36;
    constexpr int B_ELEMS = B_COL ? BN * 36 : BK * 132;
    constexpr int STAGE   = A_ELEMS + B_ELEMS;

    int bz = blockIdx.z;
    A += (size_t)bz * strA;
    B += (size_t)bz * strB;
    C += (size_t)bz * strC;
    if (res) res += (size_t)bz * strR;

    const int bm = blockIdx.y * BM;
    const int bn = blockIdx.x * BN;
    const int tid = threadIdx.x;
    const int warp = tid >> 5;
    const int wm = warp >> 1;    // 0..3 (M dir, 32 rows each)
    const int wn = warp & 1;     // 0..1 (N dir, 64 cols each)

    wmma::fragment<wmma::accumulator, 16, 16, 8, float> acc[2][4];
    #pragma unroll
    for (int i = 0; i < 2; i++)
        #pragma unroll
        for (int j = 0; j < 4; j++)
            wmma::fill_fragment(acc[i][j], 0.0f);

    auto load_tiles = [&](int stage, int k0) {
        float* sA = smem + stage * STAGE;
        float* sB = sA + A_ELEMS;
        if (A_COL) {
            // tile [BK rows][BM floats contiguous] -> sA[k*132 + m]
            #pragma unroll
            for (int c = tid; c < 1024; c += 256) {
                int k = c >> 5, m4 = (c & 31) << 2;
                cp16(&sA[k * 132 + m4], &A[(size_t)(k0 + k) * lda + bm + m4]);
            }
        } else {
            // tile [BM rows][BK floats contiguous] -> sA[m*36 + k]
            #pragma unroll
            for (int c = tid; c < 1024; c += 256) {
                int m = c >> 3, k4 = (c & 7) << 2;
                cp16(&sA[m * 36 + k4], &A[(size_t)(bm + m) * lda + k0 + k4]);
            }
        }
        if (B_COL) {
            // tile [BN rows][BK floats contiguous] -> sB[n*36 + k]
            #pragma unroll
            for (int c = tid; c < 1024; c += 256) {
                int n = c >> 3, k4 = (c & 7) << 2;
                cp16(&sB[n * 36 + k4], &B[(size_t)(bn + n) * ldb + k0 + k4]);
            }
        } else {
            // tile [BK rows][BN floats contiguous] -> sB[k*132 + n]
            #pragma unroll
            for (int c = tid; c < 1024; c += 256) {
                int k = c >> 5, n4 = (c & 31) << 2;
                cp16(&sB[k * 132 + n4], &B[(size_t)(k0 + k) * ldb + bn + n4]);
            }
        }
    };

    const int KT = K / BK;
    load_tiles(0, 0);
    asm volatile("cp.async.commit_group;");

    using ALay = typename CondLay<A_COL>::type;
    using BLay = typename CondLay<B_COL>::type;

    for (int kt = 0; kt < KT; kt++) {
        if (kt + 1 < KT) {
            load_tiles((kt + 1) & 1, (kt + 1) * BK);
            asm volatile("cp.async.commit_group;");
            asm volatile("cp.async.wait_group 1;");
        } else {
            asm volatile("cp.async.wait_group 0;");
        }
        __syncthreads();

        float* sA = smem + (kt & 1) * STAGE;
        float* sB = sA + A_ELEMS;

        #pragma unroll
        for (int kk = 0; kk < BK; kk += 8) {
            wmma::fragment<wmma::matrix_a, 16, 16, 8, wmma::precision::tf32, ALay> fa[2];
            wmma::fragment<wmma::matrix_b, 16, 16, 8, wmma::precision::tf32, BLay> fb[4];
            #pragma unroll
            for (int im = 0; im < 2; im++) {
                int m0 = wm * 32 + im * 16;
                const float* p = A_COL ? (sA + kk * 132 + m0) : (sA + (size_t)m0 * 36 + kk);
                wmma::load_matrix_sync(fa[im], p, A_COL ? 132 : 36);
                #pragma unroll
                for (int t = 0; t < fa[im].num_elements; t++)
                    fa[im].x[t] = wmma::__float_to_tf32(fa[im].x[t]);
            }
            #pragma unroll
            for (int in_ = 0; in_ < 4; in_++) {
                int n0 = wn * 64 + in_ * 16;
                const float* p = B_COL ? (sB + (size_t)n0 * 36 + kk) : (sB + kk * 132 + n0);
                wmma::load_matrix_sync(fb[in_], p, B_COL ? 36 : 132);
                #pragma unroll
                for (int t = 0; t < fb[in_].num_elements; t++)
                    fb[in_].x[t] = wmma::__float_to_tf32(fb[in_].x[t]);
            }
            #pragma unroll
            for (int im = 0; im < 2; im++)
                #pragma unroll
                for (int in_ = 0; in_ < 4; in_++)
                    wmma::mma_sync(acc[im][in_], fa[im], fb[in_], acc[im][in_]);
        }
        __syncthreads();   // all warps done reading this stage before it is refilled
    }

    // ---- epilogue: stage accums in smem (reuse pipeline buffers), then write ----
    float* sC = smem;   // viewed as [128][132]
    #pragma unroll
    for (int im = 0; im < 2; im++)
        #pragma unroll
        for (int in_ = 0; in_ < 4; in_++)
            wmma::store_matrix_sync(sC + (size_t)(wm * 32 + im * 16) * 132 + wn * 64 + in_ * 16,
                                    acc[im][in_], 132, wmma::mem_row_major);
    __syncthreads();

    for (int i = tid; i < BM * BN; i += 256) {
        int m = i >> 7, n = i & 127;
        float v = alpha * sC[(size_t)m * 132 + n];
        if (bias) v += bias[bm + m];
        if (res)  v += res[(size_t)(bm + m) * ldc + bn + n];
        C[(size_t)(bm + m) * ldc + bn + n] = v;
    }
}

// ---------------- row softmax (in-place), rows of length AREA ----------------
__global__ void softmax_kernel(float* __restrict__ S) {
    float* row = S + (size_t)blockIdx.x * AREA;
    __shared__ float buf[AREA];
    __shared__ float red[256];
    int tid = threadIdx.x;

    float m = -INFINITY;
    for (int i = tid; i < AREA; i += 256) {
        float v = row[i];
        buf[i] = v;
        m = fmaxf(m, v);
    }
    red[tid] = m;
    __syncthreads();
    for (int o = 128; o > 0; o >>= 1) {
        if (tid < o) red[tid] = fmaxf(red[tid], red[tid + o]);
        __syncthreads();
    }
    m = red[0];
    __syncthreads();

    float s = 0.f;
    for (int i = tid; i < AREA; i += 256) {
        float e = __expf(buf[i] - m);
        buf[i] = e;
        s += e;
    }
    red[tid] = s;
    __syncthreads();
    for (int o = 128; o > 0; o >>= 1) {
        if (tid < o) red[tid] += red[tid + o];
        __syncthreads();
    }
    float inv = 1.0f / red[0];
    __syncthreads();

    for (int i = tid; i < AREA; i += 256)
        row[i] = buf[i] * inv;
}

// ---------------- launch ----------------
extern "C" void kernel_launch(void* const* d_in, const int* in_sizes, int n_in,
                              void* d_out, int out_size) {
    const float* net      = (const float*)d_in[0];
    const float* gn_scale = (const float*)d_in[1];
    const float* gn_bias  = (const float*)d_in[2];
    const float* wq = (const float*)d_in[3];
    const float* bq = (const float*)d_in[4];
    const float* wk = (const float*)d_in[5];
    const float* bk = (const float*)d_in[6];
    const float* wv = (const float*)d_in[7];
    const float* bv = (const float*)d_in[8];
    const float* wo = (const float*)d_in[9];
    const float* bo = (const float*)d_in[10];
    float* out = (float*)d_out;

    float *xn, *qkv, *h, *s, *wqkv, *bqkv;
    cudaGetSymbolAddress((void**)&xn,   g_xn);
    cudaGetSymbolAddress((void**)&qkv,  g_qkv);
    cudaGetSymbolAddress((void**)&h,    g_h);
    cudaGetSymbolAddress((void**)&s,    g_s);
    cudaGetSymbolAddress((void**)&wqkv, g_wqkv);
    cudaGetSymbolAddress((void**)&bqkv, g_bqkv);

    // dynamic smem opt-in (per template instantiation)
    const int SMEM_FF = (BM * 36 + BK * 132) * 2 * 4;   // 70656
    const int SMEM_TF = (BK * 132 + BK * 132) * 2 * 4;  // 67584
    const int SMEM_FT = (BM * 36 + BN * 36) * 2 * 4;    // 73728
    cudaFuncSetAttribute(gemm_tf32<false, false>, cudaFuncAttributeMaxDynamicSharedMemorySize, SMEM_FF);
    cudaFuncSetAttribute(gemm_tf32<true,  false>, cudaFuncAttributeMaxDynamicSharedMemorySize, SMEM_TF);
    cudaFuncSetAttribute(gemm_tf32<false, true >, cudaFuncAttributeMaxDynamicSharedMemorySize, SMEM_FT);

    const long sBC  = (long)CCH * AREA;        // per-batch stride [C, area]
    const long s3BC = (long)3 * CCH * AREA;    // per-batch stride of fused qkv
    const long sSS  = (long)AREA * AREA;
    const float inv_sqrt_c = 1.0f / sqrtf((float)CCH);

    // 0. pack QKV weights
    pack_qkv_kernel<<<(CCH * CCH + 255) / 256, 256>>>(wq, wk, wv, bq, bk, bv, wqkv, bqkv);

    // 1. GroupNorm
    groupnorm_kernel<<<BATCH * GRP, 256>>>(net, gn_scale, gn_bias, xn);

    // 2. fused QKV = Wqkv @ xn + bqkv   (M=1536, N=4096, K=512)
    {
        dim3 g(AREA / BN, (3 * CCH) / BM, BATCH);
        gemm_tf32<false, false><<<g, 256, SMEM_FF>>>(wqkv, xn, qkv, bqkv, nullptr,
            3 * CCH, AREA, CCH, CCH, AREA, AREA, 0, sBC, s3BC, 0, 1.0f);
    }

    const float* q = qkv;                       // [b stride s3BC]
    const float* k = qkv + (size_t)CCH * AREA;
    const float* v = qkv + (size_t)2 * CCH * AREA;

    // 3. S = (Q^T K) / sqrt(C)   (M=4096, N=4096, K=512)
    {
        dim3 g(AREA / BN, AREA / BM, BATCH);
        gemm_tf32<true, false><<<g, 256, SMEM_TF>>>(q, k, s, nullptr, nullptr,
            AREA, AREA, CCH, AREA, AREA, AREA, s3BC, s3BC, sSS, 0, inv_sqrt_c);
    }

    // 4. softmax over keys (rows of S)
    softmax_kernel<<<BATCH * AREA, 256>>>(s);

    // 5. H = V @ P^T  (M=512, N=4096, K=4096)
    {
        dim3 g(AREA / BN, CCH / BM, BATCH);
        gemm_tf32<false, true><<<g, 256, SMEM_FT>>>(v, s, h, nullptr, nullptr,
            CCH, AREA, AREA, AREA, AREA, AREA, s3BC, sSS, sBC, 0, 1.0f);
    }

    // 6. out = net + Wo @ H + bo  (M=512, N=4096, K=512)
    {
        dim3 g(AREA / BN, CCH / BM, BATCH);
        gemm_tf32<false, false><<<g, 256, SMEM_FF>>>(wo, h, out, bo, net,
            CCH, AREA, CCH, CCH, AREA, AREA, 0, sBC, sBC, sBC, 1.0f);
    }
}

// round 7
// speedup vs baseline: 2.4483x; 1.1249x over previous
#include <cuda_runtime.h>
#include <cstdint>
#include <mma.h>
#include <math.h>

using namespace nvcuda;

#define CCH 512
#define GRP 32
#define AREA 4096
#define BATCH 4
#define EPS 1e-6f

// ---------------- scratch (device globals) ----------------
__device__ float g_xn  [(size_t)BATCH * CCH * AREA];       // 32 MB
__device__ float g_qkv [(size_t)BATCH * 3 * CCH * AREA];   // 96 MB (q|k|v per batch)
__device__ float g_h   [(size_t)BATCH * CCH * AREA];       // 32 MB
__device__ float g_s   [(size_t)BATCH * AREA * AREA];      // 256 MB
__device__ float g_wqkv[3 * CCH * CCH];
__device__ float g_bqkv[3 * CCH];

// ---------------- GroupNorm ----------------
__global__ void groupnorm_kernel(const float* __restrict__ net,
                                 const float* __restrict__ gscale,
                                 const float* __restrict__ gbias,
                                 float* __restrict__ xn) {
    const int CPG = CCH / GRP;           // 16
    const int NEL = CPG * AREA;          // 65536
    int bg = blockIdx.x;
    int b = bg / GRP, g = bg % GRP;
    const float* x = net + ((size_t)b * CCH + (size_t)g * CPG) * AREA;
    float* y = xn + ((size_t)b * CCH + (size_t)g * CPG) * AREA;

    int tid = threadIdx.x;
    float s = 0.f, ss = 0.f;
    for (int i = tid; i < NEL; i += blockDim.x) {
        float v = x[i];
        s += v; ss += v * v;
    }
    __shared__ float rs[256], rss[256];
    rs[tid] = s; rss[tid] = ss;
    __syncthreads();
    for (int o = 128; o > 0; o >>= 1) {
        if (tid < o) { rs[tid] += rs[tid + o]; rss[tid] += rss[tid + o]; }
        __syncthreads();
    }
    float mu  = rs[0] / (float)NEL;
    float var = rss[0] / (float)NEL - mu * mu;
    float inv = rsqrtf(var + EPS);

    for (int i = tid; i < NEL; i += blockDim.x) {
        int cl = i / AREA;
        int c  = g * CPG + cl;
        y[i] = (x[i] - mu) * inv * gscale[c] + gbias[c];
    }
}

// ---------------- pack QKV weights/biases ----------------
__global__ void pack_qkv_kernel(const float* __restrict__ wq, const float* __restrict__ wk,
                                const float* __restrict__ wv, const float* __restrict__ bq,
                                const float* __restrict__ bk, const float* __restrict__ bv,
                                float* __restrict__ w, float* __restrict__ b) {
    int i = blockIdx.x * blockDim.x + threadIdx.x;
    const int WN = CCH * CCH;
    if (i < WN) {
        w[i] = wq[i];
        w[i + WN] = wk[i];
        w[i + 2 * WN] = wv[i];
    }
    if (i < CCH) {
        b[i] = bq[i];
        b[i + CCH] = bk[i];
        b[i + 2 * CCH] = bv[i];
    }
}

// ---------------- double-buffered TF32 WMMA GEMM, 128x128x32 ----------------
// All shapes/strides compile-time so ptxas folds addressing -> fewer regs,
// 2 CTAs/SM. C[m,n] = alpha*sum_k A(m,k)*B(k,n) [+bias[m]] [+res].
// A_COL: A(m,k)=A[k*LDA+m]; B_COL: B(k,n)=B[n*LDB+k].
#define BM 128
#define BN 128
#define BK 32

template<bool C_> struct CondLay;
template<> struct CondLay<false> { using type = wmma::row_major; };
template<> struct CondLay<true>  { using type = wmma::col_major; };

__device__ __forceinline__ void cp16(void* s, const void* g) {
    unsigned int sa = (unsigned int)__cvta_generic_to_shared(s);
    asm volatile("cp.async.cg.shared.global [%0], [%1], 16;" :: "r"(sa), "l"(g));
}

template<int Mv, int Nv, int Kv, int LDA, int LDB, int LDC,
         bool A_COL, bool B_COL, bool HAS_BIAS, bool HAS_RES>
__global__ void __launch_bounds__(256, 2)
gemm_tf32(const float* __restrict__ A, const float* __restrict__ B,
          float* __restrict__ C,
          const float* __restrict__ bias, const float* __restrict__ res,
          long strA, long strB, long strC, long strR, float alpha) {
    extern __shared__ float smem[];
    constexpr int A_ELEMS = A_COL ? BK * 132 : BM * 36;
    constexpr int B_ELEMS = B_COL ? BN * 36 : BK * 132;
    constexpr int STAGE   = A_ELEMS + B_ELEMS;

    const int bz = blockIdx.z;
    A += (size_t)bz * strA;
    B += (size_t)bz * strB;
    C += (size_t)bz * strC;
    if (HAS_RES) res += (size_t)bz * strR;

    const int bm = blockIdx.y * BM;
    const int bn = blockIdx.x * BN;
    const int tid = threadIdx.x;
    const int warp = tid >> 5;
    const int wm = warp >> 1;    // 0..3
    const int wn = warp & 1;     // 0..1

    wmma::fragment<wmma::accumulator, 16, 16, 8, float> acc[2][4];
    #pragma unroll
    for (int i = 0; i < 2; i++)
        #pragma unroll
        for (int j = 0; j < 4; j++)
            wmma::fill_fragment(acc[i][j], 0.0f);

    auto load_tiles = [&](int stage, int k0) {
        float* sA = smem + stage * STAGE;
        float* sB = sA + A_ELEMS;
        if (A_COL) {
            #pragma unroll
            for (int c = tid; c < 1024; c += 256) {
                int k = c >> 5, m4 = (c & 31) << 2;
                cp16(&sA[k * 132 + m4], &A[(size_t)(k0 + k) * LDA + bm + m4]);
            }
        } else {
            #pragma unroll
            for (int c = tid; c < 1024; c += 256) {
                int m = c >> 3, k4 = (c & 7) << 2;
                cp16(&sA[m * 36 + k4], &A[(size_t)(bm + m) * LDA + k0 + k4]);
            }
        }
        if (B_COL) {
            #pragma unroll
            for (int c = tid; c < 1024; c += 256) {
                int n = c >> 3, k4 = (c & 7) << 2;
                cp16(&sB[n * 36 + k4], &B[(size_t)(bn + n) * LDB + k0 + k4]);
            }
        } else {
            #pragma unroll
            for (int c = tid; c < 1024; c += 256) {
                int k = c >> 5, n4 = (c & 31) << 2;
                cp16(&sB[k * 132 + n4], &B[(size_t)(k0 + k) * LDB + bn + n4]);
            }
        }
    };

    constexpr int KT = Kv / BK;
    load_tiles(0, 0);
    asm volatile("cp.async.commit_group;");

    using ALay = typename CondLay<A_COL>::type;
    using BLay = typename CondLay<B_COL>::type;

    for (int kt = 0; kt < KT; kt++) {
        if (kt + 1 < KT) {
            load_tiles((kt + 1) & 1, (kt + 1) * BK);
            asm volatile("cp.async.commit_group;");
            asm volatile("cp.async.wait_group 1;");
        } else {
            asm volatile("cp.async.wait_group 0;");
        }
        __syncthreads();

        float* sA = smem + (kt & 1) * STAGE;
        float* sB = sA + A_ELEMS;

        #pragma unroll
        for (int kk = 0; kk < BK; kk += 8) {
            wmma::fragment<wmma::matrix_a, 16, 16, 8, wmma::precision::tf32, ALay> fa[2];
            wmma::fragment<wmma::matrix_b, 16, 16, 8, wmma::precision::tf32, BLay> fb[4];
            #pragma unroll
            for (int im = 0; im < 2; im++) {
                int m0 = wm * 32 + im * 16;
                const float* p = A_COL ? (sA + kk * 132 + m0) : (sA + m0 * 36 + kk);
                wmma::load_matrix_sync(fa[im], p, A_COL ? 132 : 36);
                #pragma unroll
                for (int t = 0; t < fa[im].num_elements; t++)
                    fa[im].x[t] = wmma::__float_to_tf32(fa[im].x[t]);
            }
            #pragma unroll
            for (int in_ = 0; in_ < 4; in_++) {
                int n0 = wn * 64 + in_ * 16;
                const float* p = B_COL ? (sB + n0 * 36 + kk) : (sB + kk * 132 + n0);
                wmma::load_matrix_sync(fb[in_], p, B_COL ? 36 : 132);
                #pragma unroll
                for (int t = 0; t < fb[in_].num_elements; t++)
                    fb[in_].x[t] = wmma::__float_to_tf32(fb[in_].x[t]);
            }
            #pragma unroll
            for (int im = 0; im < 2; im++)
                #pragma unroll
                for (int in_ = 0; in_ < 4; in_++)
                    wmma::mma_sync(acc[im][in_], fa[im], fb[in_], acc[im][in_]);
        }
        __syncthreads();
    }

    // ---- epilogue: stage accums in smem, then vectorized write ----
    float* sC = smem;   // [128][132]
    #pragma unroll
    for (int im = 0; im < 2; im++)
        #pragma unroll
        for (int in_ = 0; in_ < 4; in_++)
            wmma::store_matrix_sync(sC + (wm * 32 + im * 16) * 132 + wn * 64 + in_ * 16,
                                    acc[im][in_], 132, wmma::mem_row_major);
    __syncthreads();

    #pragma unroll
    for (int i = tid; i < BM * BN / 4; i += 256) {
        int m = i >> 5, n4 = (i & 31) << 2;
        float4 v;
        v.x = alpha * sC[m * 132 + n4 + 0];
        v.y = alpha * sC[m * 132 + n4 + 1];
        v.z = alpha * sC[m * 132 + n4 + 2];
        v.w = alpha * sC[m * 132 + n4 + 3];
        if (HAS_BIAS) {
            float bb = bias[bm + m];
            v.x += bb; v.y += bb; v.z += bb; v.w += bb;
        }
        if (HAS_RES) {
            const float4 r = *(const float4*)&res[(size_t)(bm + m) * LDC + bn + n4];
            v.x += r.x; v.y += r.y; v.z += r.z; v.w += r.w;
        }
        *(float4*)&C[(size_t)(bm + m) * LDC + bn + n4] = v;
    }
}

// ---------------- row softmax (in-place), rows of length AREA ----------------
__global__ void softmax_kernel(float* __restrict__ S) {
    float* row = S + (size_t)blockIdx.x * AREA;
    __shared__ float buf[AREA];
    __shared__ float red[256];
    int tid = threadIdx.x;

    float m = -INFINITY;
    for (int i = tid; i < AREA; i += 256) {
        float v = row[i];
        buf[i] = v;
        m = fmaxf(m, v);
    }
    red[tid] = m;
    __syncthreads();
    for (int o = 128; o > 0; o >>= 1) {
        if (tid < o) red[tid] = fmaxf(red[tid], red[tid + o]);
        __syncthreads();
    }
    m = red[0];
    __syncthreads();

    float s = 0.f;
    for (int i = tid; i < AREA; i += 256) {
        float e = __expf(buf[i] - m);
        buf[i] = e;
        s += e;
    }
    red[tid] = s;
    __syncthreads();
    for (int o = 128; o > 0; o >>= 1) {
        if (tid < o) red[tid] += red[tid + o];
        __syncthreads();
    }
    float inv = 1.0f / red[0];
    __syncthreads();

    for (int i = tid; i < AREA; i += 256)
        row[i] = buf[i] * inv;
}

// ---------------- launch ----------------
extern "C" void kernel_launch(void* const* d_in, const int* in_sizes, int n_in,
                              void* d_out, int out_size) {
    const float* net      = (const float*)d_in[0];
    const float* gn_scale = (const float*)d_in[1];
    const float* gn_bias  = (const float*)d_in[2];
    const float* wq = (const float*)d_in[3];
    const float* bq = (const float*)d_in[4];
    const float* wk = (const float*)d_in[5];
    const float* bk = (const float*)d_in[6];
    const float* wv = (const float*)d_in[7];
    const float* bv = (const float*)d_in[8];
    const float* wo = (const float*)d_in[9];
    const float* bo = (const float*)d_in[10];
    float* out = (float*)d_out;

    float *xn, *qkv, *h, *s, *wqkv, *bqkv;
    cudaGetSymbolAddress((void**)&xn,   g_xn);
    cudaGetSymbolAddress((void**)&qkv,  g_qkv);
    cudaGetSymbolAddress((void**)&h,    g_h);
    cudaGetSymbolAddress((void**)&s,    g_s);
    cudaGetSymbolAddress((void**)&wqkv, g_wqkv);
    cudaGetSymbolAddress((void**)&bqkv, g_bqkv);

    const int SMEM_FF = (BM * 36 + BK * 132) * 2 * 4;   // 70656
    const int SMEM_TF = (BK * 132 + BK * 132) * 2 * 4;  // 67584
    const int SMEM_FT = (BM * 36 + BN * 36) * 2 * 4;    // 73728

    // template instantiations
    auto kQKV = gemm_tf32<3*CCH, AREA, CCH,  CCH,  AREA, AREA, false, false, true,  false>;
    auto kSC  = gemm_tf32<AREA,  AREA, CCH,  AREA, AREA, AREA, true,  false, false, false>;
    auto kPV  = gemm_tf32<CCH,   AREA, AREA, AREA, AREA, AREA, false, true,  false, false>;
    auto kOUT = gemm_tf32<CCH,   AREA, CCH,  CCH,  AREA, AREA, false, false, true,  true>;

    cudaFuncSetAttribute(kQKV, cudaFuncAttributeMaxDynamicSharedMemorySize, SMEM_FF);
    cudaFuncSetAttribute(kSC,  cudaFuncAttributeMaxDynamicSharedMemorySize, SMEM_TF);
    cudaFuncSetAttribute(kPV,  cudaFuncAttributeMaxDynamicSharedMemorySize, SMEM_FT);
    cudaFuncSetAttribute(kOUT, cudaFuncAttributeMaxDynamicSharedMemorySize, SMEM_FF);

    const long sBC  = (long)CCH * AREA;
    const long s3BC = (long)3 * CCH * AREA;
    const long sSS  = (long)AREA * AREA;
    const float inv_sqrt_c = 1.0f / sqrtf((float)CCH);

    pack_qkv_kernel<<<(CCH * CCH + 255) / 256, 256>>>(wq, wk, wv, bq, bk, bv, wqkv, bqkv);
    groupnorm_kernel<<<BATCH * GRP, 256>>>(net, gn_scale, gn_bias, xn);

    // QKV = Wqkv @ xn + b   (M=1536, N=4096, K=512)
    {
        dim3 g(AREA / BN, (3 * CCH) / BM, BATCH);
        kQKV<<<g, 256, SMEM_FF>>>(wqkv, xn, qkv, bqkv, nullptr, 0, sBC, s3BC, 0, 1.0f);
    }

    const float* q = qkv;
    const float* k = qkv + (size_t)CCH * AREA;
    const float* v = qkv + (size_t)2 * CCH * AREA;

    // S = (Q^T K) / sqrt(C)
    {
        dim3 g(AREA / BN, AREA / BM, BATCH);
        kSC<<<g, 256, SMEM_TF>>>(q, k, s, nullptr, nullptr, s3BC, s3BC, sSS, 0, inv_sqrt_c);
    }

    softmax_kernel<<<BATCH * AREA, 256>>>(s);

    // H = V @ P^T
    {
        dim3 g(AREA / BN, CCH / BM, BATCH);
        kPV<<<g, 256, SMEM_FT>>>(v, s, h, nullptr, nullptr, s3BC, sSS, sBC, 0, 1.0f);
    }

    // out = net + Wo @ H + bo
    {
        dim3 g(AREA / BN, CCH / BM, BATCH);
        kOUT<<<g, 256, SMEM_FF>>>(wo, h, out, bo, net, 0, sBC, sBC, sBC, 1.0f);
    }
}

// round 10
// speedup vs baseline: 2.5794x; 1.0535x over previous
#include <cuda_runtime.h>
#include <cstdint>
#include <mma.h>
#include <math.h>

using namespace nvcuda;

#define CCH 512
#define GRP 32
#define AREA 4096
#define BATCH 4
#define EPS 1e-6f

// ---------------- scratch (device globals) ----------------
__device__ float g_xn  [(size_t)BATCH * CCH * AREA];       // 32 MB
__device__ float g_qkv [(size_t)BATCH * 3 * CCH * AREA];   // 96 MB
__device__ float g_h   [(size_t)BATCH * CCH * AREA];       // 32 MB
__device__ float g_s   [(size_t)BATCH * AREA * AREA];      // 256 MB
__device__ float g_wqkv[3 * CCH * CCH];
__device__ float g_bqkv[3 * CCH];

// ---------------- GroupNorm ----------------
__global__ void groupnorm_kernel(const float* __restrict__ net,
                                 const float* __restrict__ gscale,
                                 const float* __restrict__ gbias,
                                 float* __restrict__ xn) {
    const int CPG = CCH / GRP;           // 16
    const int NEL = CPG * AREA;          // 65536
    int bg = blockIdx.x;
    int b = bg / GRP, g = bg % GRP;
    const float* x = net + ((size_t)b * CCH + (size_t)g * CPG) * AREA;
    float* y = xn + ((size_t)b * CCH + (size_t)g * CPG) * AREA;

    int tid = threadIdx.x;
    float s = 0.f, ss = 0.f;
    for (int i = tid; i < NEL; i += blockDim.x) {
        float v = x[i];
        s += v; ss += v * v;
    }
    __shared__ float rs[256], rss[256];
    rs[tid] = s; rss[tid] = ss;
    __syncthreads();
    for (int o = 128; o > 0; o >>= 1) {
        if (tid < o) { rs[tid] += rs[tid + o]; rss[tid] += rss[tid + o]; }
        __syncthreads();
    }
    float mu  = rs[0] / (float)NEL;
    float var = rss[0] / (float)NEL - mu * mu;
    float inv = rsqrtf(var + EPS);

    for (int i = tid; i < NEL; i += blockDim.x) {
        int cl = i / AREA;
        int c  = g * CPG + cl;
        y[i] = (x[i] - mu) * inv * gscale[c] + gbias[c];
    }
}

// ---------------- pack QKV weights/biases ----------------
__global__ void pack_qkv_kernel(const float* __restrict__ wq, const float* __restrict__ wk,
                                const float* __restrict__ wv, const float* __restrict__ bq,
                                const float* __restrict__ bk, const float* __restrict__ bv,
                                float* __restrict__ w, float* __restrict__ b) {
    int i = blockIdx.x * blockDim.x + threadIdx.x;
    const int WN = CCH * CCH;
    if (i < WN) {
        w[i] = wq[i];
        w[i + WN] = wk[i];
        w[i + 2 * WN] = wv[i];
    }
    if (i < CCH) {
        b[i] = bq[i];
        b[i + CCH] = bk[i];
        b[i + 2 * CCH] = bv[i];
    }
}

// ---------------- 3-stage cp.async TF32 WMMA GEMM, 128x128x32 ----------------
// C[m,n] = alpha*sum_k A(m,k)*B(k,n) [+bias[m]] [+res].
// A_COL: A(m,k)=A[k*LDA+m]; B_COL: B(k,n)=B[n*LDB+k].
// No explicit tf32 rounding: HMMA truncation (error << 1e-3 budget).
#define BM 128
#define BN 128
#define BK 32
#define NSTAGE 3

template<bool C_> struct CondLay;
template<> struct CondLay<false> { using type = wmma::row_major; };
template<> struct CondLay<true>  { using type = wmma::col_major; };

__device__ __forceinline__ void cp16(void* s, const void* g) {
    unsigned int sa = (unsigned int)__cvta_generic_to_shared(s);
    asm volatile("cp.async.cg.shared.global [%0], [%1], 16;" :: "r"(sa), "l"(g));
}

template<int Mv, int Nv, int Kv, int LDA, int LDB, int LDC,
         bool A_COL, bool B_COL, bool HAS_BIAS, bool HAS_RES>
__global__ void __launch_bounds__(256, 2)
gemm_tf32(const float* __restrict__ A, const float* __restrict__ B,
          float* __restrict__ C,
          const float* __restrict__ bias, const float* __restrict__ res,
          long strA, long strB, long strC, long strR, float alpha) {
    extern __shared__ float smem[];
    constexpr int A_ELEMS = A_COL ? BK * 132 : BM * 36;
    constexpr int B_ELEMS = B_COL ? BN * 36 : BK * 132;
    constexpr int STAGE   = A_ELEMS + B_ELEMS;
    constexpr int KT      = Kv / BK;

    const int bz = blockIdx.z;
    A += (size_t)bz * strA;
    B += (size_t)bz * strB;
    C += (size_t)bz * strC;
    if (HAS_RES) res += (size_t)bz * strR;

    const int bm = blockIdx.y * BM;
    const int bn = blockIdx.x * BN;
    const int tid = threadIdx.x;
    const int warp = tid >> 5;
    const int wm = warp >> 1;    // 0..3
    const int wn = warp & 1;     // 0..1

    wmma::fragment<wmma::accumulator, 16, 16, 8, float> acc[2][4];
    #pragma unroll
    for (int i = 0; i < 2; i++)
        #pragma unroll
        for (int j = 0; j < 4; j++)
            wmma::fill_fragment(acc[i][j], 0.0f);

    auto load_tiles = [&](int slot, int k0) {
        float* sA = smem + slot * STAGE;
        float* sB = sA + A_ELEMS;
        if (A_COL) {
            #pragma unroll
            for (int c = tid; c < 1024; c += 256) {
                int k = c >> 5, m4 = (c & 31) << 2;
                cp16(&sA[k * 132 + m4], &A[(size_t)(k0 + k) * LDA + bm + m4]);
            }
        } else {
            #pragma unroll
            for (int c = tid; c < 1024; c += 256) {
                int m = c >> 3, k4 = (c & 7) << 2;
                cp16(&sA[m * 36 + k4], &A[(size_t)(bm + m) * LDA + k0 + k4]);
            }
        }
        if (B_COL) {
            #pragma unroll
            for (int c = tid; c < 1024; c += 256) {
                int n = c >> 3, k4 = (c & 7) << 2;
                cp16(&sB[n * 36 + k4], &B[(size_t)(bn + n) * LDB + k0 + k4]);
            }
        } else {
            #pragma unroll
            for (int c = tid; c < 1024; c += 256) {
                int k = c >> 5, n4 = (c & 31) << 2;
                cp16(&sB[k * 132 + n4], &B[(size_t)(k0 + k) * LDB + bn + n4]);
            }
        }
    };

    // prologue: stages 0..NSTAGE-2
    #pragma unroll
    for (int s = 0; s < NSTAGE - 1; s++) {
        if (s < KT) load_tiles(s, s * BK);
        asm volatile("cp.async.commit_group;");
    }

    using ALay = typename CondLay<A_COL>::type;
    using BLay = typename CondLay<B_COL>::type;

    for (int kt = 0; kt < KT; kt++) {
        // wait for stage kt to land
        if (kt < KT - 1) asm volatile("cp.async.wait_group %0;" :: "n"(NSTAGE - 2));
        else             asm volatile("cp.async.wait_group 0;");
        __syncthreads();   // data visible; all warps done with compute(kt-1)

        // issue stage kt+NSTAGE-1 into the slot retired at kt-1
        if (kt + NSTAGE - 1 < KT)
            load_tiles((kt + NSTAGE - 1) % NSTAGE, (kt + NSTAGE - 1) * BK);
        asm volatile("cp.async.commit_group;");

        float* sA = smem + (kt % NSTAGE) * STAGE;
        float* sB = sA + A_ELEMS;

        #pragma unroll
        for (int kk = 0; kk < BK; kk += 8) {
            wmma::fragment<wmma::matrix_a, 16, 16, 8, wmma::precision::tf32, ALay> fa[2];
            wmma::fragment<wmma::matrix_b, 16, 16, 8, wmma::precision::tf32, BLay> fb[4];
            #pragma unroll
            for (int im = 0; im < 2; im++) {
                int m0 = wm * 32 + im * 16;
                const float* p = A_COL ? (sA + kk * 132 + m0) : (sA + m0 * 36 + kk);
                wmma::load_matrix_sync(fa[im], p, A_COL ? 132 : 36);
            }
            #pragma unroll
            for (int in_ = 0; in_ < 4; in_++) {
                int n0 = wn * 64 + in_ * 16;
                const float* p = B_COL ? (sB + n0 * 36 + kk) : (sB + kk * 132 + n0);
                wmma::load_matrix_sync(fb[in_], p, B_COL ? 36 : 132);
            }
            #pragma unroll
            for (int im = 0; im < 2; im++)
                #pragma unroll
                for (int in_ = 0; in_ < 4; in_++)
                    wmma::mma_sync(acc[im][in_], fa[im], fb[in_], acc[im][in_]);
        }
        // single sync per iteration (at top of next iter)
    }
    __syncthreads();   // all warps done before smem reuse as sC

    // ---- epilogue: stage accums in smem, vectorized write ----
    float* sC = smem;   // [128][132]
    #pragma unroll
    for (int im = 0; im < 2; im++)
        #pragma unroll
        for (int in_ = 0; in_ < 4; in_++)
            wmma::store_matrix_sync(sC + (wm * 32 + im * 16) * 132 + wn * 64 + in_ * 16,
                                    acc[im][in_], 132, wmma::mem_row_major);
    __syncthreads();

    #pragma unroll
    for (int i = tid; i < BM * BN / 4; i += 256) {
        int m = i >> 5, n4 = (i & 31) << 2;
        float4 v;
        v.x = alpha * sC[m * 132 + n4 + 0];
        v.y = alpha * sC[m * 132 + n4 + 1];
        v.z = alpha * sC[m * 132 + n4 + 2];
        v.w = alpha * sC[m * 132 + n4 + 3];
        if (HAS_BIAS) {
            float bb = bias[bm + m];
            v.x += bb; v.y += bb; v.z += bb; v.w += bb;
        }
        if (HAS_RES) {
            const float4 r = *(const float4*)&res[(size_t)(bm + m) * LDC + bn + n4];
            v.x += r.x; v.y += r.y; v.z += r.z; v.w += r.w;
        }
        *(float4*)&C[(size_t)(bm + m) * LDC + bn + n4] = v;
    }
}

// ---------------- row softmax (in-place), rows of length AREA ----------------
__global__ void softmax_kernel(float* __restrict__ S) {
    float* row = S + (size_t)blockIdx.x * AREA;
    __shared__ float buf[AREA];
    __shared__ float red[256];
    int tid = threadIdx.x;

    float m = -INFINITY;
    for (int i = tid; i < AREA; i += 256) {
        float v = row[i];
        buf[i] = v;
        m = fmaxf(m, v);
    }
    red[tid] = m;
    __syncthreads();
    for (int o = 128; o > 0; o >>= 1) {
        if (tid < o) red[tid] = fmaxf(red[tid], red[tid + o]);
        __syncthreads();
    }
    m = red[0];
    __syncthreads();

    float s = 0.f;
    for (int i = tid; i < AREA; i += 256) {
        float e = __expf(buf[i] - m);
        buf[i] = e;
        s += e;
    }
    red[tid] = s;
    __syncthreads();
    for (int o = 128; o > 0; o >>= 1) {
        if (tid < o) red[tid] += red[tid + o];
        __syncthreads();
    }
    float inv = 1.0f / red[0];
    __syncthreads();

    for (int i = tid; i < AREA; i += 256)
        row[i] = buf[i] * inv;
}

// ---------------- launch ----------------
extern "C" void kernel_launch(void* const* d_in, const int* in_sizes, int n_in,
                              void* d_out, int out_size) {
    const float* net      = (const float*)d_in[0];
    const float* gn_scale = (const float*)d_in[1];
    const float* gn_bias  = (const float*)d_in[2];
    const float* wq = (const float*)d_in[3];
    const float* bq = (const float*)d_in[4];
    const float* wk = (const float*)d_in[5];
    const float* bk = (const float*)d_in[6];
    const float* wv = (const float*)d_in[7];
    const float* bv = (const float*)d_in[8];
    const float* wo = (const float*)d_in[9];
    const float* bo = (const float*)d_in[10];
    float* out = (float*)d_out;

    float *xn, *qkv, *h, *s, *wqkv, *bqkv;
    cudaGetSymbolAddress((void**)&xn,   g_xn);
    cudaGetSymbolAddress((void**)&qkv,  g_qkv);
    cudaGetSymbolAddress((void**)&h,    g_h);
    cudaGetSymbolAddress((void**)&s,    g_s);
    cudaGetSymbolAddress((void**)&wqkv, g_wqkv);
    cudaGetSymbolAddress((void**)&bqkv, g_bqkv);

    const int SMEM_FF = (BM * 36 + BK * 132) * NSTAGE * 4;   // 105984
    const int SMEM_TF = (BK * 132 + BK * 132) * NSTAGE * 4;  // 101376
    const int SMEM_FT = (BM * 36 + BN * 36) * NSTAGE * 4;    // 110592

    auto kQKV = gemm_tf32<3*CCH, AREA, CCH,  CCH,  AREA, AREA, false, false, true,  false>;
    auto kSC  = gemm_tf32<AREA,  AREA, CCH,  AREA, AREA, AREA, true,  false, false, false>;
    auto kPV  = gemm_tf32<CCH,   AREA, AREA, AREA, AREA, AREA, false, true,  false, false>;
    auto kOUT = gemm_tf32<CCH,   AREA, CCH,  CCH,  AREA, AREA, false, false, true,  true>;

    cudaFuncSetAttribute(kQKV, cudaFuncAttributeMaxDynamicSharedMemorySize, SMEM_FF);
    cudaFuncSetAttribute(kSC,  cudaFuncAttributeMaxDynamicSharedMemorySize, SMEM_TF);
    cudaFuncSetAttribute(kPV,  cudaFuncAttributeMaxDynamicSharedMemorySize, SMEM_FT);
    cudaFuncSetAttribute(kOUT, cudaFuncAttributeMaxDynamicSharedMemorySize, SMEM_FF);

    const long sBC  = (long)CCH * AREA;
    const long s3BC = (long)3 * CCH * AREA;
    const long sSS  = (long)AREA * AREA;
    const float inv_sqrt_c = 1.0f / sqrtf((float)CCH);

    pack_qkv_kernel<<<(CCH * CCH + 255) / 256, 256>>>(wq, wk, wv, bq, bk, bv, wqkv, bqkv);
    groupnorm_kernel<<<BATCH * GRP, 256>>>(net, gn_scale, gn_bias, xn);

    // QKV = Wqkv @ xn + b   (M=1536, N=4096, K=512)
    {
        dim3 g(AREA / BN, (3 * CCH) / BM, BATCH);
        kQKV<<<g, 256, SMEM_FF>>>(wqkv, xn, qkv, bqkv, nullptr, 0, sBC, s3BC, 0, 1.0f);
    }

    const float* q = qkv;
    const float* k = qkv + (size_t)CCH * AREA;
    const float* v = qkv + (size_t)2 * CCH * AREA;

    // S = (Q^T K) / sqrt(C)
    {
        dim3 g(AREA / BN, AREA / BM, BATCH);
        kSC<<<g, 256, SMEM_TF>>>(q, k, s, nullptr, nullptr, s3BC, s3BC, sSS, 0, inv_sqrt_c);
    }

    softmax_kernel<<<BATCH * AREA, 256>>>(s);

    // H = V @ P^T
    {
        dim3 g(AREA / BN, CCH / BM, BATCH);
        kPV<<<g, 256, SMEM_FT>>>(v, s, h, nullptr, nullptr, s3BC, sSS, sBC, 0, 1.0f);
    }

    // out = net + Wo @ H + bo
    {
        dim3 g(AREA / BN, CCH / BM, BATCH);
        kOUT<<<g, 256, SMEM_FF>>>(wo, h, out, bo, net, 0, sBC, sBC, sBC, 1.0f);
    }
}

// round 12
// speedup vs baseline: 8.6701x; 3.3613x over previous
#include <cuda_runtime.h>
#include <cuda_fp16.h>
#include <cstdint>
#include <mma.h>
#include <math.h>

using namespace nvcuda;

#define CCH 512
#define GRP 32
#define AREA 4096
#define BATCH 4
#define EPS 1e-6f

// ---------------- scratch (device globals) ----------------
__device__ __half g_xn  [(size_t)BATCH * CCH * AREA];        // 16 MB  [b][c][pix]
__device__ __half g_qkv [(size_t)BATCH * 3 * CCH * AREA];    // 48 MB  q|k|v per batch
__device__ __half g_h   [(size_t)BATCH * CCH * AREA];        // 16 MB
__device__ float  g_s   [(size_t)BATCH * AREA * AREA];       // 256 MB scores (fp32)
__device__ __half g_p   [(size_t)BATCH * AREA * AREA];       // 128 MB softmax probs (fp16)
__device__ __half g_wqkv[3 * CCH * CCH];
__device__ __half g_wo  [CCH * CCH];
__device__ float  g_bqkv[3 * CCH];

// ---------------- GroupNorm -> half output ----------------
__global__ void groupnorm_kernel(const float* __restrict__ net,
                                 const float* __restrict__ gscale,
                                 const float* __restrict__ gbias,
                                 __half* __restrict__ xn) {
    const int CPG = CCH / GRP;           // 16
    const int NEL = CPG * AREA;          // 65536
    int bg = blockIdx.x;
    int b = bg / GRP, g = bg % GRP;
    const float* x = net + ((size_t)b * CCH + (size_t)g * CPG) * AREA;
    __half* y = xn + ((size_t)b * CCH + (size_t)g * CPG) * AREA;

    int tid = threadIdx.x;
    float s = 0.f, ss = 0.f;
    for (int i = tid; i < NEL; i += blockDim.x) {
        float v = x[i];
        s += v; ss += v * v;
    }
    __shared__ float rs[256], rss[256];
    rs[tid] = s; rss[tid] = ss;
    __syncthreads();
    for (int o = 128; o > 0; o >>= 1) {
        if (tid < o) { rs[tid] += rs[tid + o]; rss[tid] += rss[tid + o]; }
        __syncthreads();
    }
    float mu  = rs[0] / (float)NEL;
    float var = rss[0] / (float)NEL - mu * mu;
    float inv = rsqrtf(var + EPS);

    for (int i = tid; i < NEL; i += blockDim.x) {
        int cl = i / AREA;
        int c  = g * CPG + cl;
        y[i] = __float2half((x[i] - mu) * inv * gscale[c] + gbias[c]);
    }
}

// ---------------- pack weights -> half ----------------
__global__ void pack_kernel(const float* __restrict__ wq, const float* __restrict__ wk,
                            const float* __restrict__ wv, const float* __restrict__ wo,
                            const float* __restrict__ bq, const float* __restrict__ bk,
                            const float* __restrict__ bv,
                            __half* __restrict__ w, __half* __restrict__ woh,
                            float* __restrict__ b) {
    int i = blockIdx.x * blockDim.x + threadIdx.x;
    const int WN = CCH * CCH;
    if (i < WN) {
        w[i]          = __float2half(wq[i]);
        w[i + WN]     = __float2half(wk[i]);
        w[i + 2 * WN] = __float2half(wv[i]);
        woh[i]        = __float2half(wo[i]);
    }
    if (i < CCH) {
        b[i] = bq[i];
        b[i + CCH] = bk[i];
        b[i + 2 * CCH] = bv[i];
    }
}

// ---------------- 3-stage cp.async FP16 WMMA GEMM, 128x128x32 ----------------
// D[m,n] = alpha*sum_k A(m,k)*B(k,n) [+bias[m]] [+res], fp32 accumulate.
// A_COL: A(m,k)=A[k*LDA+m]; B_COL: B(k,n)=B[n*LDB+k].
// OUT_HALF: C is __half*, else float*.
#define BM 128
#define BN 128
#define BK 32
#define NSTAGE 3

template<bool C_> struct CondLay;
template<> struct CondLay<false> { using type = wmma::row_major; };
template<> struct CondLay<true>  { using type = wmma::col_major; };

__device__ __forceinline__ void cp16(void* s, const void* g) {
    unsigned int sa = (unsigned int)__cvta_generic_to_shared(s);
    asm volatile("cp.async.cg.shared.global [%0], [%1], 16;" :: "r"(sa), "l"(g));
}

#define GEMM_SMEM 67584   // max(3 stages, 128x132 f32 epilogue staging)

template<int Kv, int LDA, int LDB, int LDC,
         bool A_COL, bool B_COL, bool HAS_BIAS, bool HAS_RES, bool OUT_HALF>
__global__ void __launch_bounds__(256, 2)
gemm_fp16(const __half* __restrict__ A, const __half* __restrict__ B,
          void* __restrict__ Cv,
          const float* __restrict__ bias, const float* __restrict__ res,
          long strA, long strB, long strC, long strR, float alpha) {
    extern __shared__ __align__(16) char smem_raw[];
    __half* hm = (__half*)smem_raw;
    // half-element tile layouts:
    //  A row-major: [BM][40] ; A col-major: [BK][136]
    //  B row-major: [BK][136]; B col-major: [BN][40]
    constexpr int A_ELEMS = A_COL ? BK * 136 : BM * 40;
    constexpr int B_ELEMS = B_COL ? BN * 40 : BK * 136;
    constexpr int STAGE   = A_ELEMS + B_ELEMS;
    constexpr int KT      = Kv / BK;

    const int bz = blockIdx.z;
    A += (size_t)bz * strA;
    B += (size_t)bz * strB;
    if (HAS_RES) res += (size_t)bz * strR;

    const int bm = blockIdx.y * BM;
    const int bn = blockIdx.x * BN;
    const int tid = threadIdx.x;
    const int warp = tid >> 5;
    const int wm = warp >> 1;    // 0..3
    const int wn = warp & 1;     // 0..1

    wmma::fragment<wmma::accumulator, 16, 16, 16, float> acc[2][4];
    #pragma unroll
    for (int i = 0; i < 2; i++)
        #pragma unroll
        for (int j = 0; j < 4; j++)
            wmma::fill_fragment(acc[i][j], 0.0f);

    auto load_tiles = [&](int slot, int k0) {
        __half* sA = hm + slot * STAGE;
        __half* sB = sA + A_ELEMS;
        if (A_COL) {
            // [BK rows][BM halves] -> sA[k*136 + m]
            #pragma unroll
            for (int c = tid; c < 512; c += 256) {
                int k = c >> 4, m8 = (c & 15) << 3;
                cp16(&sA[k * 136 + m8], &A[(size_t)(k0 + k) * LDA + bm + m8]);
            }
        } else {
            // [BM rows][BK halves] -> sA[m*40 + k]
            #pragma unroll
            for (int c = tid; c < 512; c += 256) {
                int m = c >> 2, k8 = (c & 3) << 3;
                cp16(&sA[m * 40 + k8], &A[(size_t)(bm + m) * LDA + k0 + k8]);
            }
        }
        if (B_COL) {
            // [BN rows][BK halves] -> sB[n*40 + k]
            #pragma unroll
            for (int c = tid; c < 512; c += 256) {
                int n = c >> 2, k8 = (c & 3) << 3;
                cp16(&sB[n * 40 + k8], &B[(size_t)(bn + n) * LDB + k0 + k8]);
            }
        } else {
            // [BK rows][BN halves] -> sB[k*136 + n]
            #pragma unroll
            for (int c = tid; c < 512; c += 256) {
                int k = c >> 4, n8 = (c & 15) << 3;
                cp16(&sB[k * 136 + n8], &B[(size_t)(k0 + k) * LDB + bn + n8]);
            }
        }
    };

    // prologue
    #pragma unroll
    for (int s = 0; s < NSTAGE - 1; s++) {
        if (s < KT) load_tiles(s, s * BK);
        asm volatile("cp.async.commit_group;");
    }

    using ALay = typename CondLay<A_COL>::type;
    using BLay = typename CondLay<B_COL>::type;

    for (int kt = 0; kt < KT; kt++) {
        if (kt < KT - 1) asm volatile("cp.async.wait_group %0;" :: "n"(NSTAGE - 2));
        else             asm volatile("cp.async.wait_group 0;");
        __syncthreads();

        if (kt + NSTAGE - 1 < KT)
            load_tiles((kt + NSTAGE - 1) % NSTAGE, (kt + NSTAGE - 1) * BK);
        asm volatile("cp.async.commit_group;");

        __half* sA = hm + (kt % NSTAGE) * STAGE;
        __half* sB = sA + A_ELEMS;

        #pragma unroll
        for (int kk = 0; kk < BK; kk += 16) {
            wmma::fragment<wmma::matrix_a, 16, 16, 16, __half, ALay> fa[2];
            wmma::fragment<wmma::matrix_b, 16, 16, 16, __half, BLay> fb[4];
            #pragma unroll
            for (int im = 0; im < 2; im++) {
                int m0 = wm * 32 + im * 16;
                const __half* p = A_COL ? (sA + kk * 136 + m0) : (sA + m0 * 40 + kk);
                wmma::load_matrix_sync(fa[im], p, A_COL ? 136 : 40);
            }
            #pragma unroll
            for (int in_ = 0; in_ < 4; in_++) {
                int n0 = wn * 64 + in_ * 16;
                const __half* p = B_COL ? (sB + n0 * 40 + kk) : (sB + kk * 136 + n0);
                wmma::load_matrix_sync(fb[in_], p, B_COL ? 40 : 136);
            }
            #pragma unroll
            for (int im = 0; im < 2; im++)
                #pragma unroll
                for (int in_ = 0; in_ < 4; in_++)
                    wmma::mma_sync(acc[im][in_], fa[im], fb[in_], acc[im][in_]);
        }
    }
    __syncthreads();   // done with stage buffers before reuse as sC

    // ---- epilogue: stage accums in smem (fp32), then write ----
    float* sC = (float*)smem_raw;   // [128][132]
    #pragma unroll
    for (int im = 0; im < 2; im++)
        #pragma unroll
        for (int in_ = 0; in_ < 4; in_++)
            wmma::store_matrix_sync(sC + (wm * 32 + im * 16) * 132 + wn * 64 + in_ * 16,
                                    acc[im][in_], 132, wmma::mem_row_major);
    __syncthreads();

    #pragma unroll
    for (int i = tid; i < BM * BN / 4; i += 256) {
        int m = i >> 5, n4 = (i & 31) << 2;
        float4 v;
        v.x = alpha * sC[m * 132 + n4 + 0];
        v.y = alpha * sC[m * 132 + n4 + 1];
        v.z = alpha * sC[m * 132 + n4 + 2];
        v.w = alpha * sC[m * 132 + n4 + 3];
        if (HAS_BIAS) {
            float bb = bias[bm + m];
            v.x += bb; v.y += bb; v.z += bb; v.w += bb;
        }
        if (HAS_RES) {
            const float4 r = *(const float4*)&res[(size_t)(bm + m) * LDC + bn + n4];
            v.x += r.x; v.y += r.y; v.z += r.z; v.w += r.w;
        }
        if (OUT_HALF) {
            __half* Ch = (__half*)Cv + (size_t)bz * strC;
            __half2 h0 = __floats2half2_rn(v.x, v.y);
            __half2 h1 = __floats2half2_rn(v.z, v.w);
            uint2 pk = { *(uint32_t*)&h0, *(uint32_t*)&h1 };
            *(uint2*)&Ch[(size_t)(bm + m) * LDC + bn + n4] = pk;
        } else {
            float* Cf = (float*)Cv + (size_t)bz * strC;
            *(float4*)&Cf[(size_t)(bm + m) * LDC + bn + n4] = v;
        }
    }
}

// ---------------- row softmax: fp32 in, fp16 out ----------------
__global__ void softmax_kernel(const float* __restrict__ S, __half* __restrict__ P) {
    const float* row = S + (size_t)blockIdx.x * AREA;
    __half* prow = P + (size_t)blockIdx.x * AREA;
    __shared__ float buf[AREA];
    __shared__ float red[256];
    int tid = threadIdx.x;

    float m = -INFINITY;
    for (int i = tid; i < AREA; i += 256) {
        float v = row[i];
        buf[i] = v;
        m = fmaxf(m, v);
    }
    red[tid] = m;
    __syncthreads();
    for (int o = 128; o > 0; o >>= 1) {
        if (tid < o) red[tid] = fmaxf(red[tid], red[tid + o]);
        __syncthreads();
    }
    m = red[0];
    __syncthreads();

    float s = 0.f;
    for (int i = tid; i < AREA; i += 256) {
        float e = __expf(buf[i] - m);
        buf[i] = e;
        s += e;
    }
    red[tid] = s;
    __syncthreads();
    for (int o = 128; o > 0; o >>= 1) {
        if (tid < o) red[tid] += red[tid + o];
        __syncthreads();
    }
    float inv = 1.0f / red[0];
    __syncthreads();

    for (int i = tid; i < AREA; i += 256)
        prow[i] = __float2half(buf[i] * inv);
}

// ---------------- launch ----------------
extern "C" void kernel_launch(void* const* d_in, const int* in_sizes, int n_in,
                              void* d_out, int out_size) {
    const float* net      = (const float*)d_in[0];
    const float* gn_scale = (const float*)d_in[1];
    const float* gn_bias  = (const float*)d_in[2];
    const float* wq = (const float*)d_in[3];
    const float* bq = (const float*)d_in[4];
    const float* wk = (const float*)d_in[5];
    const float* bk = (const float*)d_in[6];
    const float* wv = (const float*)d_in[7];
    const float* bv = (const float*)d_in[8];
    const float* wo = (const float*)d_in[9];
    const float* bo = (const float*)d_in[10];
    float* out = (float*)d_out;

    __half *xn, *qkv, *h, *p, *wqkv, *woh;
    float *s, *bqkv;
    cudaGetSymbolAddress((void**)&xn,   g_xn);
    cudaGetSymbolAddress((void**)&qkv,  g_qkv);
    cudaGetSymbolAddress((void**)&h,    g_h);
    cudaGetSymbolAddress((void**)&s,    g_s);
    cudaGetSymbolAddress((void**)&p,    g_p);
    cudaGetSymbolAddress((void**)&wqkv, g_wqkv);
    cudaGetSymbolAddress((void**)&woh,  g_wo);
    cudaGetSymbolAddress((void**)&bqkv, g_bqkv);

    // instantiations
    auto kQKV = gemm_fp16<CCH,  CCH,  AREA, AREA, false, false, true,  false, true >;
    auto kSC  = gemm_fp16<CCH,  AREA, AREA, AREA, true,  false, false, false, false>;
    auto kPV  = gemm_fp16<AREA, AREA, AREA, AREA, false, true,  false, false, true >;
    auto kOUT = gemm_fp16<CCH,  CCH,  AREA, AREA, false, false, true,  true,  false>;

    cudaFuncSetAttribute(kQKV, cudaFuncAttributeMaxDynamicSharedMemorySize, GEMM_SMEM);
    cudaFuncSetAttribute(kSC,  cudaFuncAttributeMaxDynamicSharedMemorySize, GEMM_SMEM);
    cudaFuncSetAttribute(kPV,  cudaFuncAttributeMaxDynamicSharedMemorySize, GEMM_SMEM);
    cudaFuncSetAttribute(kOUT, cudaFuncAttributeMaxDynamicSharedMemorySize, GEMM_SMEM);

    const long sBC  = (long)CCH * AREA;
    const long s3BC = (long)3 * CCH * AREA;
    const long sSS  = (long)AREA * AREA;
    const float inv_sqrt_c = 1.0f / sqrtf((float)CCH);

    pack_kernel<<<(CCH * CCH + 255) / 256, 256>>>(wq, wk, wv, wo, bq, bk, bv,
                                                  wqkv, woh, bqkv);
    groupnorm_kernel<<<BATCH * GRP, 256>>>(net, gn_scale, gn_bias, xn);

    // QKV = Wqkv @ xn + b  (M=1536, N=4096, K=512), half out
    {
        dim3 g(AREA / BN, (3 * CCH) / BM, BATCH);
        kQKV<<<g, 256, GEMM_SMEM>>>(wqkv, xn, qkv, bqkv, nullptr, 0, sBC, s3BC, 0, 1.0f);
    }

    const __half* q = qkv;
    const __half* k = qkv + (size_t)CCH * AREA;
    const __half* v = qkv + (size_t)2 * CCH * AREA;

    // S = (Q^T K) / sqrt(C), fp32 out
    {
        dim3 g(AREA / BN, AREA / BM, BATCH);
        kSC<<<g, 256, GEMM_SMEM>>>(q, k, s, nullptr, nullptr, s3BC, s3BC, sSS, 0, inv_sqrt_c);
    }

    softmax_kernel<<<BATCH * AREA, 256>>>(s, p);

    // H = V @ P^T, half out
    {
        dim3 g(AREA / BN, CCH / BM, BATCH);
        kPV<<<g, 256, GEMM_SMEM>>>(v, p, h, nullptr, nullptr, s3BC, sSS, sBC, 0, 1.0f);
    }

    // out = net + Wo @ H + bo, fp32 out
    {
        dim3 g(AREA / BN, CCH / BM, BATCH);
        kOUT<<<g, 256, GEMM_SMEM>>>(woh, h, out, bo, net, 0, sBC, sBC, sBC, 1.0f);
    }
}